// round 14
// baseline (speedup 1.0000x reference)
#include <cuda_runtime.h>
#include <cuda_fp16.h>
#include <cstdint>

#define BATCH 4
#define SEQ   4096
#define EMBED 1024
#define HEAD  64
#define ROWS  (BATCH * SEQ)
#define KSPLIT 3

#define LOG2E 1.4426950408889634f

__device__ __half g_wh[192 * EMBED];        // fp16 W, e-window-permuted
__device__ __half g_q [ROWS * HEAD];        // fp16, h-window-permuted
__device__ __half g_k [ROWS * HEAD];        // fp16, h-window-permuted
__device__ __half g_vt[BATCH * HEAD * SEQ]; // fp16, key-window-permuted
__device__ float  g_qn[ROWS];
__device__ int    g_kmax_i[BATCH];
__device__ float  g_opart[KSPLIT * ROWS * HEAD];
__device__ float  g_l   [KSPLIT * ROWS];

// ---------------------------------------------------------------------------
__device__ __forceinline__ void mma16(float* d, unsigned a0, unsigned a1,
                                      unsigned a2, unsigned a3,
                                      unsigned b0, unsigned b1) {
    asm("mma.sync.aligned.m16n8k16.row.col.f32.f16.f16.f32 "
        "{%0,%1,%2,%3},{%4,%5,%6,%7},{%8,%9},{%0,%1,%2,%3};"
        : "+f"(d[0]), "+f"(d[1]), "+f"(d[2]), "+f"(d[3])
        : "r"(a0), "r"(a1), "r"(a2), "r"(a3), "r"(b0), "r"(b1));
}

__device__ __forceinline__ unsigned packh2(float lo, float hi) {
    __half2 h = __floats2half2_rn(lo, hi);
    return *reinterpret_cast<unsigned*>(&h);
}

// window permutation: pair p -> slot [0,2,4,6 | 1,3,5,7]
__device__ __forceinline__ int perm16(int idx) {
    int p = (idx & 15) >> 1;
    int slot = (p < 4) ? (2 * p) : (2 * p - 7);
    return (idx & ~15) + 2 * slot + (idx & 1);
}

__device__ __forceinline__ void cp16(void* sptr, const void* gaddr) {
    uint32_t sa = (uint32_t)__cvta_generic_to_shared(sptr);
    asm volatile("cp.async.ca.shared.global [%0], [%1], 16;" ::"r"(sa), "l"(gaddr));
}
__device__ __forceinline__ void cp_commit() { asm volatile("cp.async.commit_group;"); }

// ===========================================================================
// Weight convert: g_wh[n][e] = fp16(W[n][e]), e window-permuted. + kmax init
// ===========================================================================
__global__ void __launch_bounds__(256) wcvt_kernel(const float* __restrict__ Wq,
                                                   const float* __restrict__ Wk,
                                                   const float* __restrict__ Wv) {
    if (blockIdx.x == 0 && threadIdx.x < BATCH) g_kmax_i[threadIdx.x] = 0;
    int idx4 = blockIdx.x * 256 + threadIdx.x;
    int n  = idx4 >> 8;
    int e4 = idx4 & 255;
    int e  = 4 * e4;
    const float* src = (n < 64) ? Wq : (n < 128) ? Wk : Wv;
    float4 v = *(const float4*)(src + (size_t)(n & 63) * EMBED + e);
    *(__half2*)&g_wh[(size_t)n * EMBED + perm16(e)]     = __floats2half2_rn(v.x, v.y);
    *(__half2*)&g_wh[(size_t)n * EMBED + perm16(e + 2)] = __floats2half2_rn(v.z, v.w);
}

// ===========================================================================
// Projection (fp16 m16n8k16): tile 64 rows x 192 cols, 256 threads.
// 4-stage cp.async ring (3 chunks in flight), one __syncthreads per chunk.
// ===========================================================================
#define PKC   32
#define PSTR  40
#define WSTR  40
#define XS_B  (64 * PSTR * 4)           // 10240 B
#define WS_B  (192 * WSTR * 2)          // 15360 B
#define PROJ_BUF_B (XS_B + WS_B)        // 25600 B
#define PROJ_NSTAGE 4
#define PROJ_SMEM_B (PROJ_NSTAGE * PROJ_BUF_B)  // 102400 B

__global__ void __launch_bounds__(256, 2)
proj_kernel(const float* __restrict__ x) {
    extern __shared__ char smc[];
    const int t = threadIdx.x, lane = t & 31, wid = t >> 5;
    const int g = lane >> 2, tq = lane & 3;
    const int wm = wid & 1, wn = wid >> 1;
    const size_t row0 = (size_t)blockIdx.x * 64;

    float acc[2][6][4];
#pragma unroll
    for (int mt = 0; mt < 2; mt++)
#pragma unroll
        for (int nt = 0; nt < 6; nt++)
#pragma unroll
            for (int i = 0; i < 4; i++) acc[mt][nt][i] = 0.f;

    const int NC = EMBED / PKC;   // 32

    auto issue = [&](int c) {
        char* buf = smc + (c & 3) * PROJ_BUF_B;
        float*  Xs = (float*)buf;
        __half* Ws = (__half*)(buf + XS_B);
        int k0 = c * PKC;
#pragma unroll
        for (int j = 0; j < 2; j++) {            // X: 64 rows x 32 f = 512 float4
            int id = t + 256 * j;
            int r = id >> 3, q = id & 7;
            cp16(&Xs[r * PSTR + 4 * q], x + (row0 + r) * EMBED + k0 + 4 * q);
        }
#pragma unroll
        for (int j = 0; j < 3; j++) {            // W: 192 rows x 32 h = 768 x 8h
            int id = t + 256 * j;
            int n = id >> 2, q = id & 3;
            cp16(&Ws[n * WSTR + 8 * q], g_wh + (size_t)n * EMBED + k0 + 8 * q);
        }
        cp_commit();
    };

    issue(0); issue(1); issue(2);
    for (int c = 0; c < NC; c++) {
        if (c < NC - 2)       asm volatile("cp.async.wait_group 2;");
        else if (c == NC - 2) asm volatile("cp.async.wait_group 1;");
        else                  asm volatile("cp.async.wait_group 0;");
        __syncthreads();
        if (c + 3 < NC) issue(c + 3);

        const char* buf = smc + (c & 3) * PROJ_BUF_B;
        const float*  Xs = (const float*)buf;
        const __half* Ws = (const __half*)(buf + XS_B);
#pragma unroll
        for (int kk = 0; kk < 2; kk++) {
            unsigned a[2][4];
#pragma unroll
            for (int mt = 0; mt < 2; mt++) {
                int r = 32 * wm + 16 * mt + g;
                float2 la = *(const float2*)&Xs[(r    ) * PSTR + 16 * kk + 2 * tq];
                float2 ha = *(const float2*)&Xs[(r + 8) * PSTR + 16 * kk + 2 * tq];
                float2 lb = *(const float2*)&Xs[(r    ) * PSTR + 16 * kk + 8 + 2 * tq];
                float2 hb = *(const float2*)&Xs[(r + 8) * PSTR + 16 * kk + 8 + 2 * tq];
                a[mt][0] = packh2(la.x, la.y);
                a[mt][1] = packh2(ha.x, ha.y);
                a[mt][2] = packh2(lb.x, lb.y);
                a[mt][3] = packh2(hb.x, hb.y);
            }
#pragma unroll
            for (int nt = 0; nt < 6; nt++) {
                uint2 bb = *(const uint2*)&Ws[(48 * wn + 8 * nt + g) * WSTR
                                              + 16 * kk + 4 * tq];
#pragma unroll
                for (int mt = 0; mt < 2; mt++)
                    mma16(acc[mt][nt], a[mt][0], a[mt][1], a[mt][2], a[mt][3],
                          bb.x, bb.y);
            }
        }
    }

#pragma unroll
    for (int mt = 0; mt < 2; mt++) {
#pragma unroll
        for (int nt = 0; nt < 6; nt++) {
            int c0 = 48 * wn + 8 * nt + 2 * tq;
            int msel = c0 >> 6;
            int h    = c0 & 63;
            int r1 = (int)row0 + 32 * wm + 16 * mt + g;
            int r2 = r1 + 8;
            float* a = acc[mt][nt];
            if (msel == 0) {
                int hp = perm16(h);
                *(__half2*)&g_q[(size_t)r1 * 64 + hp] = __floats2half2_rn(a[0], a[1]);
                *(__half2*)&g_q[(size_t)r2 * 64 + hp] = __floats2half2_rn(a[2], a[3]);
            } else if (msel == 1) {
                int hp = perm16(h);
                *(__half2*)&g_k[(size_t)r1 * 64 + hp] = __floats2half2_rn(a[0], a[1]);
                *(__half2*)&g_k[(size_t)r2 * 64 + hp] = __floats2half2_rn(a[2], a[3]);
            } else {
                int b1 = r1 >> 12, n1 = r1 & 4095;
                int b2 = r2 >> 12, n2 = r2 & 4095;
                int np1 = perm16(n1), np2 = perm16(n2);
                g_vt[((size_t)b1 * 64 + h    ) * SEQ + np1] = __float2half_rn(a[0]);
                g_vt[((size_t)b1 * 64 + h + 1) * SEQ + np1] = __float2half_rn(a[1]);
                g_vt[((size_t)b2 * 64 + h    ) * SEQ + np2] = __float2half_rn(a[2]);
                g_vt[((size_t)b2 * 64 + h + 1) * SEQ + np2] = __float2half_rn(a[3]);
            }
        }
    }
}

// ===========================================================================
// Norms (over the fp16 values actually fed to the mma; perm-invariant)
// ===========================================================================
__global__ void __launch_bounds__(128) norm_kernel() {
    int row = blockIdx.x * 128 + threadIdx.x;
    const __half2* qrow = (const __half2*)&g_q[(size_t)row * 64];
    const __half2* krow = (const __half2*)&g_k[(size_t)row * 64];
    float nq = 0.f, nk = 0.f;
#pragma unroll
    for (int i = 0; i < 32; i++) {
        float2 qf = __half22float2(qrow[i]);
        float2 kf = __half22float2(krow[i]);
        nq += qf.x * qf.x + qf.y * qf.y;
        nk += kf.x * kf.x + kf.y * kf.y;
    }
    g_qn[row] = sqrtf(nq);
    float nkr = sqrtf(nk);
#pragma unroll
    for (int d = 16; d; d >>= 1)
        nkr = fmaxf(nkr, __shfl_xor_sync(0xffffffffu, nkr, d));
    if ((threadIdx.x & 31) == 0)
        atomicMax(&g_kmax_i[row >> 12], __float_as_int(nkr));
}

// ===========================================================================
// Flash attention, fp16 m16n8k16, static max, fused S->exp->PV.
// Dedicated Q buffer + 3-stage K/V ring (2 tiles in flight), ONE sync/tile.
// 128 threads (4 warps x 32 rows), 3 CTAs/SM, grid 384 (split-K x3).
// ===========================================================================
#define STRH  72                        // halves per row (144 B)
#define QBUF_B (128 * STRH * 2)         // 18432 B
#define RING_SLOT_B (2 * 64 * STRH * 2) // K + V per tile = 18432 B
#define RING_OFF QBUF_B
#define MASK_OFF (RING_OFF + 3 * RING_SLOT_B)   // 73728
#define ATTN_SMEM_B (MASK_OFF + 3 * 64 * 4)     // 74496 B

__global__ void __launch_bounds__(128, 3)
attn_kernel(const int* __restrict__ mask) {
    extern __shared__ char smb[];
    __half* Qs = (__half*)smb;
    float*  Mb = (float*)(smb + MASK_OFF);

    const int t = threadIdx.x, lane = t & 31;
    const int g = lane >> 2, tq = lane & 3;
    const int r0 = (t >> 5) * 32;
    const int b  = blockIdx.y, z = blockIdx.z;
    const int q0 = blockIdx.x * 128;

    const int startTile = (z == 0) ? 0 : 22 + 21 * (z - 1);
    const int ntz       = (z == 0) ? 22 : 21;
    const int koff      = startTile * 64;

    const __half* qbase = g_q + ((size_t)b * SEQ + q0) * HEAD;
    const __half* kbase = g_k + ((size_t)b * SEQ + koff) * HEAD;
    const __half* vbase = g_vt + (size_t)b * HEAD * SEQ + koff;

    auto region = [&](int it) -> __half* {
        return (__half*)(smb + RING_OFF + (it % 3) * RING_SLOT_B);
    };

    // ---- stage Q (group 0) ----
#pragma unroll
    for (int j = 0; j < 8; j++) {
        int id = t + 128 * j;
        int r = id >> 3, q = id & 7;
        cp16(&Qs[r * STRH + 8 * q], qbase + (size_t)r * 64 + 8 * q);
    }
    cp_commit();

    auto issue = [&](int it) {
        __half* Ks = region(it);
        __half* Vs = Ks + 64 * STRH;
#pragma unroll
        for (int j = 0; j < 8; j++) {
            int id = t + 128 * j;
            int r = id >> 3, q = id & 7;
            if (r < 64)
                cp16(&Ks[r * STRH + 8 * q],
                     kbase + (size_t)(it * 64 + r) * 64 + 8 * q);
            else
                cp16(&Vs[(r - 64) * STRH + 8 * q],
                     vbase + (size_t)(r - 64) * SEQ + it * 64 + 8 * q);
        }
        if (t < 64)
            Mb[(it % 3) * 64 + t] =
                (mask[b * SEQ + koff + it * 64 + t] == 0) ? 0.f : 1.f;
        cp_commit();
    };

    issue(0);

    const float SC2 = 0.125f * LOG2E;
    const float kmax = __int_as_float(g_kmax_i[b]);
    float negM[2][2];
#pragma unroll
    for (int rg = 0; rg < 2; rg++) {
        size_t rr = (size_t)b * SEQ + q0 + r0 + 16 * rg + g;
        negM[rg][0] = -g_qn[rr]     * kmax * SC2;
        negM[rg][1] = -g_qn[rr + 8] * kmax * SC2;
    }

    asm volatile("cp.async.wait_group 1;");   // Q group drained
    __syncthreads();

    // ---- hoist Q fragments (Q buffer is dedicated; never recycled) ----
    unsigned qa[2][4][4];
#pragma unroll
    for (int rg = 0; rg < 2; rg++)
#pragma unroll
        for (int kk = 0; kk < 4; kk++) {
            int rlo = r0 + 16 * rg + g;
            uint2 ulo = *(const uint2*)&Qs[rlo * STRH + 16 * kk + 4 * tq];
            uint2 uhi = *(const uint2*)&Qs[(rlo + 8) * STRH + 16 * kk + 4 * tq];
            qa[rg][kk][0] = ulo.x;
            qa[rg][kk][1] = uhi.x;
            qa[rg][kk][2] = ulo.y;
            qa[rg][kk][3] = uhi.y;
        }
    if (1 < ntz) issue(1);

    float l[2][2] = {{0.f, 0.f}, {0.f, 0.f}};
    float o[2][8][4];
#pragma unroll
    for (int rg = 0; rg < 2; rg++)
#pragma unroll
        for (int nt = 0; nt < 8; nt++)
#pragma unroll
            for (int i = 0; i < 4; i++) o[rg][nt][i] = 0.f;

    for (int it = 0; it < ntz; it++) {
        // stage(it) done; stage(it+1) may remain in flight
        if (it + 1 < ntz) asm volatile("cp.async.wait_group 1;");
        else              asm volatile("cp.async.wait_group 0;");
        __syncthreads();                 // also guards ring slot reuse below
        if (it + 2 < ntz) issue(it + 2); // slot (it+2)%3 == (it-1)%3, now free

        const __half* Ks = region(it);
        const __half* Vs = Ks + 64 * STRH;
        const float*  mk = Mb + (it % 3) * 64;

#pragma unroll
        for (int w = 0; w < 4; w++) {
            float s[2][2][4];
#pragma unroll
            for (int c = 0; c < 2; c++)
#pragma unroll
                for (int rg = 0; rg < 2; rg++)
#pragma unroll
                    for (int i = 0; i < 4; i++) s[c][rg][i] = 0.f;
#pragma unroll
            for (int c = 0; c < 2; c++) {
                int nt = 2 * w + c;
#pragma unroll
                for (int kk = 0; kk < 4; kk++) {
                    uint2 bb = *(const uint2*)&Ks[(8 * nt + g) * STRH + 16 * kk + 4 * tq];
                    mma16(s[c][0], qa[0][kk][0], qa[0][kk][1], qa[0][kk][2],
                          qa[0][kk][3], bb.x, bb.y);
                    mma16(s[c][1], qa[1][kk][0], qa[1][kk][1], qa[1][kk][2],
                          qa[1][kk][3], bb.x, bb.y);
                }
            }
            unsigned pa[2][4];
#pragma unroll
            for (int c = 0; c < 2; c++) {
                float2 mm = *(const float2*)&mk[8 * (2 * w + c) + 2 * tq];
#pragma unroll
                for (int rg = 0; rg < 2; rg++) {
                    float p0 = exp2f(fmaf(s[c][rg][0], SC2, negM[rg][0])) * mm.x;
                    float p1 = exp2f(fmaf(s[c][rg][1], SC2, negM[rg][0])) * mm.y;
                    float p2 = exp2f(fmaf(s[c][rg][2], SC2, negM[rg][1])) * mm.x;
                    float p3 = exp2f(fmaf(s[c][rg][3], SC2, negM[rg][1])) * mm.y;
                    l[rg][0] += p0 + p1;
                    l[rg][1] += p2 + p3;
                    pa[rg][2 * c    ] = packh2(p0, p1);
                    pa[rg][2 * c + 1] = packh2(p2, p3);
                }
            }
#pragma unroll
            for (int nh = 0; nh < 8; nh++) {
                uint2 bb = *(const uint2*)&Vs[(8 * nh + g) * STRH + 16 * w + 4 * tq];
                mma16(o[0][nh], pa[0][0], pa[0][1], pa[0][2], pa[0][3], bb.x, bb.y);
                mma16(o[1][nh], pa[1][0], pa[1][1], pa[1][2], pa[1][3], bb.x, bb.y);
            }
        }
    }

    // ---- epilogue: reduce l across tq, store unnormalized O + l ----
#pragma unroll
    for (int rg = 0; rg < 2; rg++)
#pragma unroll
        for (int h = 0; h < 2; h++) {
            l[rg][h] += __shfl_xor_sync(0xffffffffu, l[rg][h], 1);
            l[rg][h] += __shfl_xor_sync(0xffffffffu, l[rg][h], 2);
        }
#pragma unroll
    for (int rg = 0; rg < 2; rg++) {
        size_t rlo = (size_t)z * ROWS + (size_t)b * SEQ + q0 + r0 + 16 * rg + g;
        size_t rhi = rlo + 8;
#pragma unroll
        for (int nt = 0; nt < 8; nt++) {
            int c0 = 8 * nt + 2 * tq;
            *(float2*)&g_opart[rlo * 64 + c0] = make_float2(o[rg][nt][0], o[rg][nt][1]);
            *(float2*)&g_opart[rhi * 64 + c0] = make_float2(o[rg][nt][2], o[rg][nt][3]);
        }
        if (tq == 0) {
            g_l[rlo] = l[rg][0];
            g_l[rhi] = l[rg][1];
        }
    }
}

// ===========================================================================
// Split-K combine
// ===========================================================================
__global__ void __launch_bounds__(256) combine_kernel(float* __restrict__ out) {
    int t = threadIdx.x;
    int row = blockIdx.x * 16 + (t >> 4);
    int c   = (t & 15) * 4;
    float lsum = g_l[row] + g_l[ROWS + row] + g_l[2 * ROWS + row];
    float inv = 1.f / lsum;
    float4 a = *(const float4*)&g_opart[(size_t)row * 64 + c];
    float4 d = *(const float4*)&g_opart[((size_t)ROWS + row) * 64 + c];
    float4 e = *(const float4*)&g_opart[((size_t)2 * ROWS + row) * 64 + c];
    float4 r = make_float4((a.x + d.x + e.x) * inv, (a.y + d.y + e.y) * inv,
                           (a.z + d.z + e.z) * inv, (a.w + d.w + e.w) * inv);
    *(float4*)&out[(size_t)row * 64 + c] = r;
}

// ---------------------------------------------------------------------------
extern "C" void kernel_launch(void* const* d_in, const int* in_sizes, int n_in,
                              void* d_out, int out_size) {
    const float* x    = (const float*)d_in[0];
    const float* Wq   = (const float*)d_in[1];
    const float* Wk   = (const float*)d_in[2];
    const float* Wv   = (const float*)d_in[3];
    const int*   mask = (const int*)d_in[4];
    float*       out  = (float*)d_out;

    cudaFuncSetAttribute(proj_kernel, cudaFuncAttributeMaxDynamicSharedMemorySize,
                         PROJ_SMEM_B);
    cudaFuncSetAttribute(attn_kernel, cudaFuncAttributeMaxDynamicSharedMemorySize,
                         ATTN_SMEM_B);

    wcvt_kernel<<<192, 256>>>(Wq, Wk, Wv);
    proj_kernel<<<ROWS / 64, 256, PROJ_SMEM_B>>>(x);
    norm_kernel<<<ROWS / 128, 128>>>();
    attn_kernel<<<dim3(SEQ / 128, BATCH, KSPLIT), 128, ATTN_SMEM_B>>>(mask);
    combine_kernel<<<ROWS / 16, 256>>>(out);
}

// round 15
// speedup vs baseline: 1.3131x; 1.3131x over previous
#include <cuda_runtime.h>
#include <cuda_fp16.h>
#include <cstdint>

#define BATCH 4
#define SEQ   4096
#define EMBED 1024
#define HEAD  64
#define ROWS  (BATCH * SEQ)
#define KSPLIT 3

#define LOG2E 1.4426950408889634f

__device__ __half g_wh[192 * EMBED];        // fp16 W, e-window-permuted
__device__ __half g_q [ROWS * HEAD];        // fp16, h-window-permuted
__device__ __half g_k [ROWS * HEAD];        // fp16, h-window-permuted
__device__ __half g_vt[BATCH * HEAD * SEQ]; // fp16, key-window-permuted
__device__ float  g_qn[ROWS];
__device__ int    g_kmax_i[BATCH];
__device__ float  g_opart[KSPLIT * ROWS * HEAD];
__device__ float  g_l   [KSPLIT * ROWS];

// ---------------------------------------------------------------------------
__device__ __forceinline__ void mma16(float* d, unsigned a0, unsigned a1,
                                      unsigned a2, unsigned a3,
                                      unsigned b0, unsigned b1) {
    asm("mma.sync.aligned.m16n8k16.row.col.f32.f16.f16.f32 "
        "{%0,%1,%2,%3},{%4,%5,%6,%7},{%8,%9},{%0,%1,%2,%3};"
        : "+f"(d[0]), "+f"(d[1]), "+f"(d[2]), "+f"(d[3])
        : "r"(a0), "r"(a1), "r"(a2), "r"(a3), "r"(b0), "r"(b1));
}

__device__ __forceinline__ unsigned packh2(float lo, float hi) {
    __half2 h = __floats2half2_rn(lo, hi);
    return *reinterpret_cast<unsigned*>(&h);
}

// window permutation: pair p -> slot [0,2,4,6 | 1,3,5,7]
__device__ __forceinline__ int perm16(int idx) {
    int p = (idx & 15) >> 1;
    int slot = (p < 4) ? (2 * p) : (2 * p - 7);
    return (idx & ~15) + 2 * slot + (idx & 1);
}

__device__ __forceinline__ void cp16(void* sptr, const void* gaddr) {
    uint32_t sa = (uint32_t)__cvta_generic_to_shared(sptr);
    asm volatile("cp.async.ca.shared.global [%0], [%1], 16;" ::"r"(sa), "l"(gaddr));
}
__device__ __forceinline__ void cp_commit() { asm volatile("cp.async.commit_group;"); }

// ===========================================================================
// Weight convert: g_wh[n][e] = fp16(W[n][e]), e window-permuted. + kmax init
// ===========================================================================
__global__ void __launch_bounds__(256) wcvt_kernel(const float* __restrict__ Wq,
                                                   const float* __restrict__ Wk,
                                                   const float* __restrict__ Wv) {
    if (blockIdx.x == 0 && threadIdx.x < BATCH) g_kmax_i[threadIdx.x] = 0;
    int idx4 = blockIdx.x * 256 + threadIdx.x;
    int n  = idx4 >> 8;
    int e4 = idx4 & 255;
    int e  = 4 * e4;
    const float* src = (n < 64) ? Wq : (n < 128) ? Wk : Wv;
    float4 v = *(const float4*)(src + (size_t)(n & 63) * EMBED + e);
    *(__half2*)&g_wh[(size_t)n * EMBED + perm16(e)]     = __floats2half2_rn(v.x, v.y);
    *(__half2*)&g_wh[(size_t)n * EMBED + perm16(e + 2)] = __floats2half2_rn(v.z, v.w);
}

// ===========================================================================
// Projection (fp16 m16n8k16): tile 64 rows x 192 cols, 256 threads.
// PKC=64 double buffer (R12 control flow, 2x stage size -> 2x prefetch lead,
// half the per-chunk overhead). X PSTR=72 f / W WSTR=80 h: conflict-free.
// ===========================================================================
#define PKC   64
#define PSTR  72                        // floats per X row
#define WSTR  80                        // halves per W row
#define XS_B  (64 * PSTR * 4)           // 18432 B
#define WS_B  (192 * WSTR * 2)          // 30720 B
#define PROJ_BUF_B (XS_B + WS_B)        // 49152 B
#define PROJ_SMEM_B (2 * PROJ_BUF_B)    // 98304 B

__global__ void __launch_bounds__(256, 2)
proj_kernel(const float* __restrict__ x) {
    extern __shared__ char smc[];
    const int t = threadIdx.x, lane = t & 31, wid = t >> 5;
    const int g = lane >> 2, tq = lane & 3;
    const int wm = wid & 1, wn = wid >> 1;
    const size_t row0 = (size_t)blockIdx.x * 64;

    float acc[2][6][4];
#pragma unroll
    for (int mt = 0; mt < 2; mt++)
#pragma unroll
        for (int nt = 0; nt < 6; nt++)
#pragma unroll
            for (int i = 0; i < 4; i++) acc[mt][nt][i] = 0.f;

    const int NC = EMBED / PKC;   // 16

    auto issue = [&](int c) {
        char* buf = smc + (c & 1) * PROJ_BUF_B;
        float*  Xs = (float*)buf;
        __half* Ws = (__half*)(buf + XS_B);
        int k0 = c * PKC;
#pragma unroll
        for (int j = 0; j < 4; j++) {            // X: 64 rows x 64 f = 1024 float4
            int id = t + 256 * j;
            int r = id >> 4, q = id & 15;
            cp16(&Xs[r * PSTR + 4 * q], x + (row0 + r) * EMBED + k0 + 4 * q);
        }
#pragma unroll
        for (int j = 0; j < 6; j++) {            // W: 192 rows x 64 h = 1536 x 8h
            int id = t + 256 * j;
            int n = id >> 3, q = id & 7;
            cp16(&Ws[n * WSTR + 8 * q], g_wh + (size_t)n * EMBED + k0 + 8 * q);
        }
        cp_commit();
    };

    issue(0);
    for (int c = 0; c < NC; c++) {
        if (c + 1 < NC) {
            issue(c + 1);
            asm volatile("cp.async.wait_group 1;");
        } else {
            asm volatile("cp.async.wait_group 0;");
        }
        __syncthreads();
        const char* buf = smc + (c & 1) * PROJ_BUF_B;
        const float*  Xs = (const float*)buf;
        const __half* Ws = (const __half*)(buf + XS_B);
#pragma unroll
        for (int kk = 0; kk < 4; kk++) {         // four k16 windows per chunk
            unsigned a[2][4];
#pragma unroll
            for (int mt = 0; mt < 2; mt++) {
                int r = 32 * wm + 16 * mt + g;
                float2 la = *(const float2*)&Xs[(r    ) * PSTR + 16 * kk + 2 * tq];
                float2 ha = *(const float2*)&Xs[(r + 8) * PSTR + 16 * kk + 2 * tq];
                float2 lb = *(const float2*)&Xs[(r    ) * PSTR + 16 * kk + 8 + 2 * tq];
                float2 hb = *(const float2*)&Xs[(r + 8) * PSTR + 16 * kk + 8 + 2 * tq];
                a[mt][0] = packh2(la.x, la.y);
                a[mt][1] = packh2(ha.x, ha.y);
                a[mt][2] = packh2(lb.x, lb.y);
                a[mt][3] = packh2(hb.x, hb.y);
            }
#pragma unroll
            for (int nt = 0; nt < 6; nt++) {
                uint2 bb = *(const uint2*)&Ws[(48 * wn + 8 * nt + g) * WSTR
                                              + 16 * kk + 4 * tq];
#pragma unroll
                for (int mt = 0; mt < 2; mt++)
                    mma16(acc[mt][nt], a[mt][0], a[mt][1], a[mt][2], a[mt][3],
                          bb.x, bb.y);
            }
        }
        __syncthreads();
    }

#pragma unroll
    for (int mt = 0; mt < 2; mt++) {
#pragma unroll
        for (int nt = 0; nt < 6; nt++) {
            int c0 = 48 * wn + 8 * nt + 2 * tq;
            int msel = c0 >> 6;
            int h    = c0 & 63;
            int r1 = (int)row0 + 32 * wm + 16 * mt + g;
            int r2 = r1 + 8;
            float* a = acc[mt][nt];
            if (msel == 0) {
                int hp = perm16(h);
                *(__half2*)&g_q[(size_t)r1 * 64 + hp] = __floats2half2_rn(a[0], a[1]);
                *(__half2*)&g_q[(size_t)r2 * 64 + hp] = __floats2half2_rn(a[2], a[3]);
            } else if (msel == 1) {
                int hp = perm16(h);
                *(__half2*)&g_k[(size_t)r1 * 64 + hp] = __floats2half2_rn(a[0], a[1]);
                *(__half2*)&g_k[(size_t)r2 * 64 + hp] = __floats2half2_rn(a[2], a[3]);
            } else {
                int b1 = r1 >> 12, n1 = r1 & 4095;
                int b2 = r2 >> 12, n2 = r2 & 4095;
                int np1 = perm16(n1), np2 = perm16(n2);
                g_vt[((size_t)b1 * 64 + h    ) * SEQ + np1] = __float2half_rn(a[0]);
                g_vt[((size_t)b1 * 64 + h + 1) * SEQ + np1] = __float2half_rn(a[1]);
                g_vt[((size_t)b2 * 64 + h    ) * SEQ + np2] = __float2half_rn(a[2]);
                g_vt[((size_t)b2 * 64 + h + 1) * SEQ + np2] = __float2half_rn(a[3]);
            }
        }
    }
}

// ===========================================================================
// Norms (over the fp16 values actually fed to the mma; perm-invariant)
// ===========================================================================
__global__ void __launch_bounds__(128) norm_kernel() {
    int row = blockIdx.x * 128 + threadIdx.x;
    const __half2* qrow = (const __half2*)&g_q[(size_t)row * 64];
    const __half2* krow = (const __half2*)&g_k[(size_t)row * 64];
    float nq = 0.f, nk = 0.f;
#pragma unroll
    for (int i = 0; i < 32; i++) {
        float2 qf = __half22float2(qrow[i]);
        float2 kf = __half22float2(krow[i]);
        nq += qf.x * qf.x + qf.y * qf.y;
        nk += kf.x * kf.x + kf.y * kf.y;
    }
    g_qn[row] = sqrtf(nq);
    float nkr = sqrtf(nk);
#pragma unroll
    for (int d = 16; d; d >>= 1)
        nkr = fmaxf(nkr, __shfl_xor_sync(0xffffffffu, nkr, d));
    if ((threadIdx.x & 31) == 0)
        atomicMax(&g_kmax_i[row >> 12], __float_as_int(nkr));
}

// ===========================================================================
// Flash attention, fp16 m16n8k16, static max, fused S->exp->PV. (R12 exact)
// ===========================================================================
#define STRH  72
#define REG_H (128 * STRH)
#define ATTN_SMEM_B (2 * REG_H * 2 + 512)

__global__ void __launch_bounds__(128, 3)
attn_kernel(const int* __restrict__ mask) {
    extern __shared__ char smb[];
    __half* HA = (__half*)smb;
    __half* HB = HA + REG_H;
    float*  Mb = (float*)(smb + 2 * REG_H * 2);

    const int t = threadIdx.x, lane = t & 31;
    const int g = lane >> 2, tq = lane & 3;
    const int r0 = (t >> 5) * 32;
    const int b  = blockIdx.y, z = blockIdx.z;
    const int q0 = blockIdx.x * 128;

    const int startTile = (z == 0) ? 0 : 22 + 21 * (z - 1);
    const int ntz       = (z == 0) ? 22 : 21;
    const int koff      = startTile * 64;

    const __half* qbase = g_q + ((size_t)b * SEQ + q0) * HEAD;
    const __half* kbase = g_k + ((size_t)b * SEQ + koff) * HEAD;
    const __half* vbase = g_vt + (size_t)b * HEAD * SEQ + koff;

    auto region = [&](int it) -> __half* { return (it & 1) ? HA : HB; };

#pragma unroll
    for (int j = 0; j < 8; j++) {
        int id = t + 128 * j;
        int r = id >> 3, q = id & 7;
        cp16(&HA[r * STRH + 8 * q], qbase + (size_t)r * 64 + 8 * q);
    }
    cp_commit();

    auto issue = [&](int it) {
        __half* Ks = region(it);
        __half* Vs = Ks + 64 * STRH;
#pragma unroll
        for (int j = 0; j < 8; j++) {
            int id = t + 128 * j;
            int r = id >> 3, q = id & 7;
            if (r < 64)
                cp16(&Ks[r * STRH + 8 * q],
                     kbase + (size_t)(it * 64 + r) * 64 + 8 * q);
            else
                cp16(&Vs[(r - 64) * STRH + 8 * q],
                     vbase + (size_t)(r - 64) * SEQ + it * 64 + 8 * q);
        }
        if (t < 64)
            Mb[(it & 1) * 64 + t] =
                (mask[b * SEQ + koff + it * 64 + t] == 0) ? 0.f : 1.f;
        cp_commit();
    };

    issue(0);

    const float SC2 = 0.125f * LOG2E;
    const float kmax = __int_as_float(g_kmax_i[b]);
    float negM[2][2];
#pragma unroll
    for (int rg = 0; rg < 2; rg++) {
        size_t rr = (size_t)b * SEQ + q0 + r0 + 16 * rg + g;
        negM[rg][0] = -g_qn[rr]     * kmax * SC2;
        negM[rg][1] = -g_qn[rr + 8] * kmax * SC2;
    }

    asm volatile("cp.async.wait_group 1;");
    __syncthreads();

    unsigned qa[2][4][4];
#pragma unroll
    for (int rg = 0; rg < 2; rg++)
#pragma unroll
        for (int kk = 0; kk < 4; kk++) {
            int rlo = r0 + 16 * rg + g;
            uint2 ulo = *(const uint2*)&HA[rlo * STRH + 16 * kk + 4 * tq];
            uint2 uhi = *(const uint2*)&HA[(rlo + 8) * STRH + 16 * kk + 4 * tq];
            qa[rg][kk][0] = ulo.x;
            qa[rg][kk][1] = uhi.x;
            qa[rg][kk][2] = ulo.y;
            qa[rg][kk][3] = uhi.y;
        }
    __syncthreads();
    if (1 < ntz) issue(1);

    float l[2][2] = {{0.f, 0.f}, {0.f, 0.f}};
    float o[2][8][4];
#pragma unroll
    for (int rg = 0; rg < 2; rg++)
#pragma unroll
        for (int nt = 0; nt < 8; nt++)
#pragma unroll
            for (int i = 0; i < 4; i++) o[rg][nt][i] = 0.f;

    for (int it = 0; it < ntz; it++) {
        if (it >= 1 && it + 1 < ntz) issue(it + 1);
        if (it + 1 < ntz) {
            asm volatile("cp.async.wait_group 1;");
        } else {
            asm volatile("cp.async.wait_group 0;");
        }
        __syncthreads();
        const __half* Ks = region(it);
        const __half* Vs = Ks + 64 * STRH;
        const float*  mk = Mb + (it & 1) * 64;

#pragma unroll
        for (int w = 0; w < 4; w++) {
            float s[2][2][4];
#pragma unroll
            for (int c = 0; c < 2; c++)
#pragma unroll
                for (int rg = 0; rg < 2; rg++)
#pragma unroll
                    for (int i = 0; i < 4; i++) s[c][rg][i] = 0.f;
#pragma unroll
            for (int c = 0; c < 2; c++) {
                int nt = 2 * w + c;
#pragma unroll
                for (int kk = 0; kk < 4; kk++) {
                    uint2 bb = *(const uint2*)&Ks[(8 * nt + g) * STRH + 16 * kk + 4 * tq];
                    mma16(s[c][0], qa[0][kk][0], qa[0][kk][1], qa[0][kk][2],
                          qa[0][kk][3], bb.x, bb.y);
                    mma16(s[c][1], qa[1][kk][0], qa[1][kk][1], qa[1][kk][2],
                          qa[1][kk][3], bb.x, bb.y);
                }
            }
            unsigned pa[2][4];
#pragma unroll
            for (int c = 0; c < 2; c++) {
                float2 mm = *(const float2*)&mk[8 * (2 * w + c) + 2 * tq];
#pragma unroll
                for (int rg = 0; rg < 2; rg++) {
                    float p0 = exp2f(fmaf(s[c][rg][0], SC2, negM[rg][0])) * mm.x;
                    float p1 = exp2f(fmaf(s[c][rg][1], SC2, negM[rg][0])) * mm.y;
                    float p2 = exp2f(fmaf(s[c][rg][2], SC2, negM[rg][1])) * mm.x;
                    float p3 = exp2f(fmaf(s[c][rg][3], SC2, negM[rg][1])) * mm.y;
                    l[rg][0] += p0 + p1;
                    l[rg][1] += p2 + p3;
                    pa[rg][2 * c    ] = packh2(p0, p1);
                    pa[rg][2 * c + 1] = packh2(p2, p3);
                }
            }
#pragma unroll
            for (int nh = 0; nh < 8; nh++) {
                uint2 bb = *(const uint2*)&Vs[(8 * nh + g) * STRH + 16 * w + 4 * tq];
                mma16(o[0][nh], pa[0][0], pa[0][1], pa[0][2], pa[0][3], bb.x, bb.y);
                mma16(o[1][nh], pa[1][0], pa[1][1], pa[1][2], pa[1][3], bb.x, bb.y);
            }
        }
        __syncthreads();
    }

#pragma unroll
    for (int rg = 0; rg < 2; rg++)
#pragma unroll
        for (int h = 0; h < 2; h++) {
            l[rg][h] += __shfl_xor_sync(0xffffffffu, l[rg][h], 1);
            l[rg][h] += __shfl_xor_sync(0xffffffffu, l[rg][h], 2);
        }
#pragma unroll
    for (int rg = 0; rg < 2; rg++) {
        size_t rlo = (size_t)z * ROWS + (size_t)b * SEQ + q0 + r0 + 16 * rg + g;
        size_t rhi = rlo + 8;
#pragma unroll
        for (int nt = 0; nt < 8; nt++) {
            int c0 = 8 * nt + 2 * tq;
            *(float2*)&g_opart[rlo * 64 + c0] = make_float2(o[rg][nt][0], o[rg][nt][1]);
            *(float2*)&g_opart[rhi * 64 + c0] = make_float2(o[rg][nt][2], o[rg][nt][3]);
        }
        if (tq == 0) {
            g_l[rlo] = l[rg][0];
            g_l[rhi] = l[rg][1];
        }
    }
}

// ===========================================================================
// Split-K combine
// ===========================================================================
__global__ void __launch_bounds__(256) combine_kernel(float* __restrict__ out) {
    int t = threadIdx.x;
    int row = blockIdx.x * 16 + (t >> 4);
    int c   = (t & 15) * 4;
    float lsum = g_l[row] + g_l[ROWS + row] + g_l[2 * ROWS + row];
    float inv = 1.f / lsum;
    float4 a = *(const float4*)&g_opart[(size_t)row * 64 + c];
    float4 d = *(const float4*)&g_opart[((size_t)ROWS + row) * 64 + c];
    float4 e = *(const float4*)&g_opart[((size_t)2 * ROWS + row) * 64 + c];
    float4 r = make_float4((a.x + d.x + e.x) * inv, (a.y + d.y + e.y) * inv,
                           (a.z + d.z + e.z) * inv, (a.w + d.w + e.w) * inv);
    *(float4*)&out[(size_t)row * 64 + c] = r;
}

// ---------------------------------------------------------------------------
extern "C" void kernel_launch(void* const* d_in, const int* in_sizes, int n_in,
                              void* d_out, int out_size) {
    const float* x    = (const float*)d_in[0];
    const float* Wq   = (const float*)d_in[1];
    const float* Wk   = (const float*)d_in[2];
    const float* Wv   = (const float*)d_in[3];
    const int*   mask = (const int*)d_in[4];
    float*       out  = (float*)d_out;

    cudaFuncSetAttribute(proj_kernel, cudaFuncAttributeMaxDynamicSharedMemorySize,
                         PROJ_SMEM_B);
    cudaFuncSetAttribute(attn_kernel, cudaFuncAttributeMaxDynamicSharedMemorySize,
                         ATTN_SMEM_B);

    wcvt_kernel<<<192, 256>>>(Wq, Wk, Wv);
    proj_kernel<<<ROWS / 64, 256, PROJ_SMEM_B>>>(x);
    norm_kernel<<<ROWS / 128, 128>>>();
    attn_kernel<<<dim3(SEQ / 128, BATCH, KSPLIT), 128, ATTN_SMEM_B>>>(mask);
    combine_kernel<<<ROWS / 16, 256>>>(out);
}

// round 16
// speedup vs baseline: 1.3273x; 1.0108x over previous
#include <cuda_runtime.h>
#include <cuda_fp16.h>
#include <cstdint>

#define BATCH 4
#define SEQ   4096
#define EMBED 1024
#define HEAD  64
#define ROWS  (BATCH * SEQ)
#define KSPLIT 3

#define LOG2E 1.4426950408889634f

__device__ __half g_wh[192 * EMBED];        // fp16 W, e-window-permuted
__device__ __half g_q [ROWS * HEAD];        // fp16, h-window-permuted
__device__ __half g_k [ROWS * HEAD];        // fp16, h-window-permuted
__device__ __half g_vt[BATCH * HEAD * SEQ]; // fp16, key-window-permuted
__device__ float  g_qn[ROWS];
__device__ int    g_kmax_i[BATCH];
__device__ float  g_opart[KSPLIT * ROWS * HEAD];
__device__ float  g_l   [KSPLIT * ROWS];

// ---------------------------------------------------------------------------
__device__ __forceinline__ void mma16(float* d, unsigned a0, unsigned a1,
                                      unsigned a2, unsigned a3,
                                      unsigned b0, unsigned b1) {
    asm("mma.sync.aligned.m16n8k16.row.col.f32.f16.f16.f32 "
        "{%0,%1,%2,%3},{%4,%5,%6,%7},{%8,%9},{%0,%1,%2,%3};"
        : "+f"(d[0]), "+f"(d[1]), "+f"(d[2]), "+f"(d[3])
        : "r"(a0), "r"(a1), "r"(a2), "r"(a3), "r"(b0), "r"(b1));
}

__device__ __forceinline__ unsigned packh2(float lo, float hi) {
    __half2 h = __floats2half2_rn(lo, hi);
    return *reinterpret_cast<unsigned*>(&h);
}

// window permutation: pair p -> slot [0,2,4,6 | 1,3,5,7]
__device__ __forceinline__ int perm16(int idx) {
    int p = (idx & 15) >> 1;
    int slot = (p < 4) ? (2 * p) : (2 * p - 7);
    return (idx & ~15) + 2 * slot + (idx & 1);
}

__device__ __forceinline__ void cp16(void* sptr, const void* gaddr) {
    uint32_t sa = (uint32_t)__cvta_generic_to_shared(sptr);
    asm volatile("cp.async.ca.shared.global [%0], [%1], 16;" ::"r"(sa), "l"(gaddr));
}
__device__ __forceinline__ void cp_commit() { asm volatile("cp.async.commit_group;"); }

// ===========================================================================
// Weight convert: g_wh[n][e] = fp16(W[n][e]), e window-permuted. + kmax init
// ===========================================================================
__global__ void __launch_bounds__(256) wcvt_kernel(const float* __restrict__ Wq,
                                                   const float* __restrict__ Wk,
                                                   const float* __restrict__ Wv) {
    if (blockIdx.x == 0 && threadIdx.x < BATCH) g_kmax_i[threadIdx.x] = 0;
    int idx4 = blockIdx.x * 256 + threadIdx.x;
    int n  = idx4 >> 8;
    int e4 = idx4 & 255;
    int e  = 4 * e4;
    const float* src = (n < 64) ? Wq : (n < 128) ? Wk : Wv;
    float4 v = *(const float4*)(src + (size_t)(n & 63) * EMBED + e);
    *(__half2*)&g_wh[(size_t)n * EMBED + perm16(e)]     = __floats2half2_rn(v.x, v.y);
    *(__half2*)&g_wh[(size_t)n * EMBED + perm16(e + 2)] = __floats2half2_rn(v.z, v.w);
}

// ===========================================================================
// Projection (fp16 m16n8k16): tile 64 rows x 192 cols, 256 threads, PKC=64
// double buffer. Epilogue also computes ||q||, ||k|| per row (over the
// fp16-rounded values) and the per-batch kmax — norm_kernel is gone.
// ===========================================================================
#define PKC   64
#define PSTR  72                        // floats per X row
#define WSTR  80                        // halves per W row
#define XS_B  (64 * PSTR * 4)           // 18432 B
#define WS_B  (192 * WSTR * 2)          // 30720 B
#define PROJ_BUF_B (XS_B + WS_B)        // 49152 B
#define PROJ_SMEM_B (2 * PROJ_BUF_B)    // 98304 B

__global__ void __launch_bounds__(256, 2)
proj_kernel(const float* __restrict__ x) {
    extern __shared__ char smc[];
    __shared__ float sq[64], sk[64];
    const int t = threadIdx.x, lane = t & 31, wid = t >> 5;
    const int g = lane >> 2, tq = lane & 3;
    const int wm = wid & 1, wn = wid >> 1;
    const size_t row0 = (size_t)blockIdx.x * 64;

    if (t < 64) { sq[t] = 0.f; sk[t] = 0.f; }

    float acc[2][6][4];
#pragma unroll
    for (int mt = 0; mt < 2; mt++)
#pragma unroll
        for (int nt = 0; nt < 6; nt++)
#pragma unroll
            for (int i = 0; i < 4; i++) acc[mt][nt][i] = 0.f;

    const int NC = EMBED / PKC;   // 16

    auto issue = [&](int c) {
        char* buf = smc + (c & 1) * PROJ_BUF_B;
        float*  Xs = (float*)buf;
        __half* Ws = (__half*)(buf + XS_B);
        int k0 = c * PKC;
#pragma unroll
        for (int j = 0; j < 4; j++) {            // X: 64 rows x 64 f = 1024 float4
            int id = t + 256 * j;
            int r = id >> 4, q = id & 15;
            cp16(&Xs[r * PSTR + 4 * q], x + (row0 + r) * EMBED + k0 + 4 * q);
        }
#pragma unroll
        for (int j = 0; j < 6; j++) {            // W: 192 rows x 64 h = 1536 x 8h
            int id = t + 256 * j;
            int n = id >> 3, q = id & 7;
            cp16(&Ws[n * WSTR + 8 * q], g_wh + (size_t)n * EMBED + k0 + 8 * q);
        }
        cp_commit();
    };

    issue(0);
    for (int c = 0; c < NC; c++) {
        if (c + 1 < NC) {
            issue(c + 1);
            asm volatile("cp.async.wait_group 1;");
        } else {
            asm volatile("cp.async.wait_group 0;");
        }
        __syncthreads();
        const char* buf = smc + (c & 1) * PROJ_BUF_B;
        const float*  Xs = (const float*)buf;
        const __half* Ws = (const __half*)(buf + XS_B);
#pragma unroll
        for (int kk = 0; kk < 4; kk++) {
            unsigned a[2][4];
#pragma unroll
            for (int mt = 0; mt < 2; mt++) {
                int r = 32 * wm + 16 * mt + g;
                float2 la = *(const float2*)&Xs[(r    ) * PSTR + 16 * kk + 2 * tq];
                float2 ha = *(const float2*)&Xs[(r + 8) * PSTR + 16 * kk + 2 * tq];
                float2 lb = *(const float2*)&Xs[(r    ) * PSTR + 16 * kk + 8 + 2 * tq];
                float2 hb = *(const float2*)&Xs[(r + 8) * PSTR + 16 * kk + 8 + 2 * tq];
                a[mt][0] = packh2(la.x, la.y);
                a[mt][1] = packh2(ha.x, ha.y);
                a[mt][2] = packh2(lb.x, lb.y);
                a[mt][3] = packh2(hb.x, hb.y);
            }
#pragma unroll
            for (int nt = 0; nt < 6; nt++) {
                uint2 bb = *(const uint2*)&Ws[(48 * wn + 8 * nt + g) * WSTR
                                              + 16 * kk + 4 * tq];
#pragma unroll
                for (int mt = 0; mt < 2; mt++)
                    mma16(acc[mt][nt], a[mt][0], a[mt][1], a[mt][2], a[mt][3],
                          bb.x, bb.y);
            }
        }
        __syncthreads();
    }

#pragma unroll
    for (int mt = 0; mt < 2; mt++) {
#pragma unroll
        for (int nt = 0; nt < 6; nt++) {
            int c0 = 48 * wn + 8 * nt + 2 * tq;
            int msel = c0 >> 6;
            int h    = c0 & 63;
            int r1 = (int)row0 + 32 * wm + 16 * mt + g;
            int r2 = r1 + 8;
            float* a = acc[mt][nt];
            if (msel == 0) {
                int hp = perm16(h);
                __half2 h1 = __floats2half2_rn(a[0], a[1]);
                __half2 h2 = __floats2half2_rn(a[2], a[3]);
                *(__half2*)&g_q[(size_t)r1 * 64 + hp] = h1;
                *(__half2*)&g_q[(size_t)r2 * 64 + hp] = h2;
                float2 f1 = __half22float2(h1), f2 = __half22float2(h2);
                atomicAdd(&sq[r1 - (int)row0], f1.x * f1.x + f1.y * f1.y);
                atomicAdd(&sq[r2 - (int)row0], f2.x * f2.x + f2.y * f2.y);
            } else if (msel == 1) {
                int hp = perm16(h);
                __half2 h1 = __floats2half2_rn(a[0], a[1]);
                __half2 h2 = __floats2half2_rn(a[2], a[3]);
                *(__half2*)&g_k[(size_t)r1 * 64 + hp] = h1;
                *(__half2*)&g_k[(size_t)r2 * 64 + hp] = h2;
                float2 f1 = __half22float2(h1), f2 = __half22float2(h2);
                atomicAdd(&sk[r1 - (int)row0], f1.x * f1.x + f1.y * f1.y);
                atomicAdd(&sk[r2 - (int)row0], f2.x * f2.x + f2.y * f2.y);
            } else {
                int b1 = r1 >> 12, n1 = r1 & 4095;
                int b2 = r2 >> 12, n2 = r2 & 4095;
                int np1 = perm16(n1), np2 = perm16(n2);
                g_vt[((size_t)b1 * 64 + h    ) * SEQ + np1] = __float2half_rn(a[0]);
                g_vt[((size_t)b1 * 64 + h + 1) * SEQ + np1] = __float2half_rn(a[1]);
                g_vt[((size_t)b2 * 64 + h    ) * SEQ + np2] = __float2half_rn(a[2]);
                g_vt[((size_t)b2 * 64 + h + 1) * SEQ + np2] = __float2half_rn(a[3]);
            }
        }
    }
    __syncthreads();
    if (t < 64) {
        g_qn[row0 + t] = sqrtf(sq[t]);
        float nkr = sqrtf(sk[t]);
#pragma unroll
        for (int d = 16; d; d >>= 1)
            nkr = fmaxf(nkr, __shfl_xor_sync(0xffffffffu, nkr, d));
        if (lane == 0)
            atomicMax(&g_kmax_i[(int)(row0 >> 12)], __float_as_int(nkr));
    }
}

// ===========================================================================
// Flash attention, fp16 m16n8k16, static max, fused S->exp->PV. (R15 exact)
// ===========================================================================
#define STRH  72
#define REG_H (128 * STRH)
#define ATTN_SMEM_B (2 * REG_H * 2 + 512)

__global__ void __launch_bounds__(128, 3)
attn_kernel(const int* __restrict__ mask) {
    extern __shared__ char smb[];
    __half* HA = (__half*)smb;
    __half* HB = HA + REG_H;
    float*  Mb = (float*)(smb + 2 * REG_H * 2);

    const int t = threadIdx.x, lane = t & 31;
    const int g = lane >> 2, tq = lane & 3;
    const int r0 = (t >> 5) * 32;
    const int b  = blockIdx.y, z = blockIdx.z;
    const int q0 = blockIdx.x * 128;

    const int startTile = (z == 0) ? 0 : 22 + 21 * (z - 1);
    const int ntz       = (z == 0) ? 22 : 21;
    const int koff      = startTile * 64;

    const __half* qbase = g_q + ((size_t)b * SEQ + q0) * HEAD;
    const __half* kbase = g_k + ((size_t)b * SEQ + koff) * HEAD;
    const __half* vbase = g_vt + (size_t)b * HEAD * SEQ + koff;

    auto region = [&](int it) -> __half* { return (it & 1) ? HA : HB; };

#pragma unroll
    for (int j = 0; j < 8; j++) {
        int id = t + 128 * j;
        int r = id >> 3, q = id & 7;
        cp16(&HA[r * STRH + 8 * q], qbase + (size_t)r * 64 + 8 * q);
    }
    cp_commit();

    auto issue = [&](int it) {
        __half* Ks = region(it);
        __half* Vs = Ks + 64 * STRH;
#pragma unroll
        for (int j = 0; j < 8; j++) {
            int id = t + 128 * j;
            int r = id >> 3, q = id & 7;
            if (r < 64)
                cp16(&Ks[r * STRH + 8 * q],
                     kbase + (size_t)(it * 64 + r) * 64 + 8 * q);
            else
                cp16(&Vs[(r - 64) * STRH + 8 * q],
                     vbase + (size_t)(r - 64) * SEQ + it * 64 + 8 * q);
        }
        if (t < 64)
            Mb[(it & 1) * 64 + t] =
                (mask[b * SEQ + koff + it * 64 + t] == 0) ? 0.f : 1.f;
        cp_commit();
    };

    issue(0);

    const float SC2 = 0.125f * LOG2E;
    const float kmax = __int_as_float(g_kmax_i[b]);
    float negM[2][2];
#pragma unroll
    for (int rg = 0; rg < 2; rg++) {
        size_t rr = (size_t)b * SEQ + q0 + r0 + 16 * rg + g;
        negM[rg][0] = -g_qn[rr]     * kmax * SC2;
        negM[rg][1] = -g_qn[rr + 8] * kmax * SC2;
    }

    asm volatile("cp.async.wait_group 1;");
    __syncthreads();

    unsigned qa[2][4][4];
#pragma unroll
    for (int rg = 0; rg < 2; rg++)
#pragma unroll
        for (int kk = 0; kk < 4; kk++) {
            int rlo = r0 + 16 * rg + g;
            uint2 ulo = *(const uint2*)&HA[rlo * STRH + 16 * kk + 4 * tq];
            uint2 uhi = *(const uint2*)&HA[(rlo + 8) * STRH + 16 * kk + 4 * tq];
            qa[rg][kk][0] = ulo.x;
            qa[rg][kk][1] = uhi.x;
            qa[rg][kk][2] = ulo.y;
            qa[rg][kk][3] = uhi.y;
        }
    __syncthreads();
    if (1 < ntz) issue(1);

    float l[2][2] = {{0.f, 0.f}, {0.f, 0.f}};
    float o[2][8][4];
#pragma unroll
    for (int rg = 0; rg < 2; rg++)
#pragma unroll
        for (int nt = 0; nt < 8; nt++)
#pragma unroll
            for (int i = 0; i < 4; i++) o[rg][nt][i] = 0.f;

    for (int it = 0; it < ntz; it++) {
        if (it >= 1 && it + 1 < ntz) issue(it + 1);
        if (it + 1 < ntz) {
            asm volatile("cp.async.wait_group 1;");
        } else {
            asm volatile("cp.async.wait_group 0;");
        }
        __syncthreads();
        const __half* Ks = region(it);
        const __half* Vs = Ks + 64 * STRH;
        const float*  mk = Mb + (it & 1) * 64;

#pragma unroll
        for (int w = 0; w < 4; w++) {
            float s[2][2][4];
#pragma unroll
            for (int c = 0; c < 2; c++)
#pragma unroll
                for (int rg = 0; rg < 2; rg++)
#pragma unroll
                    for (int i = 0; i < 4; i++) s[c][rg][i] = 0.f;
#pragma unroll
            for (int c = 0; c < 2; c++) {
                int nt = 2 * w + c;
#pragma unroll
                for (int kk = 0; kk < 4; kk++) {
                    uint2 bb = *(const uint2*)&Ks[(8 * nt + g) * STRH + 16 * kk + 4 * tq];
                    mma16(s[c][0], qa[0][kk][0], qa[0][kk][1], qa[0][kk][2],
                          qa[0][kk][3], bb.x, bb.y);
                    mma16(s[c][1], qa[1][kk][0], qa[1][kk][1], qa[1][kk][2],
                          qa[1][kk][3], bb.x, bb.y);
                }
            }
            unsigned pa[2][4];
#pragma unroll
            for (int c = 0; c < 2; c++) {
                float2 mm = *(const float2*)&mk[8 * (2 * w + c) + 2 * tq];
#pragma unroll
                for (int rg = 0; rg < 2; rg++) {
                    float p0 = exp2f(fmaf(s[c][rg][0], SC2, negM[rg][0])) * mm.x;
                    float p1 = exp2f(fmaf(s[c][rg][1], SC2, negM[rg][0])) * mm.y;
                    float p2 = exp2f(fmaf(s[c][rg][2], SC2, negM[rg][1])) * mm.x;
                    float p3 = exp2f(fmaf(s[c][rg][3], SC2, negM[rg][1])) * mm.y;
                    l[rg][0] += p0 + p1;
                    l[rg][1] += p2 + p3;
                    pa[rg][2 * c    ] = packh2(p0, p1);
                    pa[rg][2 * c + 1] = packh2(p2, p3);
                }
            }
#pragma unroll
            for (int nh = 0; nh < 8; nh++) {
                uint2 bb = *(const uint2*)&Vs[(8 * nh + g) * STRH + 16 * w + 4 * tq];
                mma16(o[0][nh], pa[0][0], pa[0][1], pa[0][2], pa[0][3], bb.x, bb.y);
                mma16(o[1][nh], pa[1][0], pa[1][1], pa[1][2], pa[1][3], bb.x, bb.y);
            }
        }
        __syncthreads();
    }

#pragma unroll
    for (int rg = 0; rg < 2; rg++)
#pragma unroll
        for (int h = 0; h < 2; h++) {
            l[rg][h] += __shfl_xor_sync(0xffffffffu, l[rg][h], 1);
            l[rg][h] += __shfl_xor_sync(0xffffffffu, l[rg][h], 2);
        }
#pragma unroll
    for (int rg = 0; rg < 2; rg++) {
        size_t rlo = (size_t)z * ROWS + (size_t)b * SEQ + q0 + r0 + 16 * rg + g;
        size_t rhi = rlo + 8;
#pragma unroll
        for (int nt = 0; nt < 8; nt++) {
            int c0 = 8 * nt + 2 * tq;
            *(float2*)&g_opart[rlo * 64 + c0] = make_float2(o[rg][nt][0], o[rg][nt][1]);
            *(float2*)&g_opart[rhi * 64 + c0] = make_float2(o[rg][nt][2], o[rg][nt][3]);
        }
        if (tq == 0) {
            g_l[rlo] = l[rg][0];
            g_l[rhi] = l[rg][1];
        }
    }
}

// ===========================================================================
// Split-K combine: 2 rows per thread (6 independent loads in flight)
// ===========================================================================
__global__ void __launch_bounds__(256) combine_kernel(float* __restrict__ out) {
    int t = threadIdx.x;
    int r0 = blockIdx.x * 32 + (t >> 4);
    int c  = (t & 15) * 4;
#pragma unroll
    for (int rr = 0; rr < 2; rr++) {
        int row = r0 + 16 * rr;
        float lsum = g_l[row] + g_l[ROWS + row] + g_l[2 * ROWS + row];
        float inv = 1.f / lsum;
        float4 a = *(const float4*)&g_opart[(size_t)row * 64 + c];
        float4 d = *(const float4*)&g_opart[((size_t)ROWS + row) * 64 + c];
        float4 e = *(const float4*)&g_opart[((size_t)2 * ROWS + row) * 64 + c];
        float4 r = make_float4((a.x + d.x + e.x) * inv, (a.y + d.y + e.y) * inv,
                               (a.z + d.z + e.z) * inv, (a.w + d.w + e.w) * inv);
        *(float4*)&out[(size_t)row * 64 + c] = r;
    }
}

// ---------------------------------------------------------------------------
extern "C" void kernel_launch(void* const* d_in, const int* in_sizes, int n_in,
                              void* d_out, int out_size) {
    const float* x    = (const float*)d_in[0];
    const float* Wq   = (const float*)d_in[1];
    const float* Wk   = (const float*)d_in[2];
    const float* Wv   = (const float*)d_in[3];
    const int*   mask = (const int*)d_in[4];
    float*       out  = (float*)d_out;

    cudaFuncSetAttribute(proj_kernel, cudaFuncAttributeMaxDynamicSharedMemorySize,
                         PROJ_SMEM_B);
    cudaFuncSetAttribute(attn_kernel, cudaFuncAttributeMaxDynamicSharedMemorySize,
                         ATTN_SMEM_B);

    wcvt_kernel<<<192, 256>>>(Wq, Wk, Wv);
    proj_kernel<<<ROWS / 64, 256, PROJ_SMEM_B>>>(x);
    attn_kernel<<<dim3(SEQ / 128, BATCH, KSPLIT), 128, ATTN_SMEM_B>>>(mask);
    combine_kernel<<<ROWS / 32, 256>>>(out);
}